// round 14
// baseline (speedup 1.0000x reference)
#include <cuda_runtime.h>
#include <cstdint>

#define T_MAX 512
#define B_SZ  64
#define IND   300
#define DIM   1024
#define TD    (T_MAX * DIM)
#define NCTA  128
#define NGRP  4
#define PST   33

// per-producer sequence numbers, padded to 128B lines: slot (grp,lcta) at
// g_seq[(grp*32 + lcta)*32]. Producer stores t+1 after finishing step t.
__device__ unsigned g_seq[NGRP * 32 * 32];
__device__ int      g_len[B_SZ];

union F2U { float2 f; unsigned long long u; };

__device__ __forceinline__ unsigned long long fma2(unsigned long long a,
                                                   unsigned long long b,
                                                   unsigned long long c) {
    unsigned long long d;
    asm("fma.rn.f32x2 %0, %1, %2, %3;" : "=l"(d) : "l"(a), "l"(b), "l"(c));
    return d;
}
__device__ __forceinline__ unsigned long long add2(unsigned long long a,
                                                   unsigned long long b) {
    unsigned long long d;
    asm("add.rn.f32x2 %0, %1, %2;" : "=l"(d) : "l"(a), "l"(b));
    return d;
}

// ---------------------------------------------------------------------------
__global__ void zero_kernel() {
    int i = blockIdx.x * blockDim.x + threadIdx.x;
    if (i < NGRP * 32 * 32) g_seq[i] = 0u;
    if (i < B_SZ)           g_len[i] = 0;
}

// ---------------------------------------------------------------------------
__global__ void __launch_bounds__(256) prep_kernel(const float* __restrict__ emb) {
    int b  = blockIdx.x & 63;
    int tq = blockIdx.x >> 6;
    int row = threadIdx.x >> 2;
    int l4  = threadIdx.x & 3;
    int t = tq * 64 + row;
    const float* p = emb + ((size_t)t * B_SZ + b) * IND;
    float s = 0.f;
    for (int i = l4; i < IND; i += 4) s += p[i];
    s += __shfl_xor_sync(~0u, s, 1);
    s += __shfl_xor_sync(~0u, s, 2);
    unsigned ball = __ballot_sync(~0u, (l4 == 0) && (s != 0.f));
    if ((threadIdx.x & 31) == 0) atomicAdd(&g_len[b], __popc(ball));
}

// ---------------------------------------------------------------------------
__global__ void tail_kernel(float* __restrict__ out, int out_size) {
    int b = threadIdx.x;
    long long tail = (long long)T_MAX * B_SZ * DIM;
    if (b < B_SZ && (long long)out_size >= tail + B_SZ)
        out[tail + b] = (float)g_len[b];
}

// ---------------------------------------------------------------------------
// ugemm: 64m x 128n tile, micro 8m x 4n (unchanged from R11).
// ---------------------------------------------------------------------------
#define KT 32
__global__ void __launch_bounds__(256) ugemm_kernel(const float* __restrict__ emb,
                                                    const float* __restrict__ win,
                                                    const float* __restrict__ bias,
                                                    float* __restrict__ out) {
    __shared__ float As[KT][68];
    __shared__ float Bs[KT][136];

    const int t  = blockIdx.x;
    const int n0 = blockIdx.y * 128;
    const int tid = threadIdx.x;
    const int tx = tid & 31, ty = tid >> 5;
    const float* arow = emb + (size_t)t * B_SZ * IND;

    float acc[8][4];
    #pragma unroll
    for (int i = 0; i < 8; i++)
        #pragma unroll
        for (int j = 0; j < 4; j++) acc[i][j] = 0.f;

    for (int kk = 0; kk < IND; kk += KT) {
        #pragma unroll
        for (int s = 0; s < 2; s++) {
            int idx = tid + s * 256;
            int row = idx >> 3;
            int f4  = idx & 7;
            int k   = kk + f4 * 4;
            float4 va = make_float4(0.f, 0.f, 0.f, 0.f);
            if (k < IND) va = *(const float4*)(arow + (size_t)row * IND + k);
            As[f4 * 4 + 0][row] = va.x; As[f4 * 4 + 1][row] = va.y;
            As[f4 * 4 + 2][row] = va.z; As[f4 * 4 + 3][row] = va.w;
        }
        #pragma unroll
        for (int s = 0; s < 4; s++) {
            int idx = tid + s * 256;
            int row = idx >> 3;
            int f4  = idx & 7;
            int k   = kk + f4 * 4;
            float4 vb = make_float4(0.f, 0.f, 0.f, 0.f);
            if (k < IND) vb = *(const float4*)(win + (size_t)(n0 + row) * IND + k);
            Bs[f4 * 4 + 0][row] = vb.x; Bs[f4 * 4 + 1][row] = vb.y;
            Bs[f4 * 4 + 2][row] = vb.z; Bs[f4 * 4 + 3][row] = vb.w;
        }
        __syncthreads();

        #pragma unroll
        for (int k = 0; k < KT; k++) {
            float4 a0 = *(const float4*)&As[k][ty * 8];
            float4 a1 = *(const float4*)&As[k][ty * 8 + 4];
            float4 bv = *(const float4*)&Bs[k][tx * 4];
            float av[8] = {a0.x, a0.y, a0.z, a0.w, a1.x, a1.y, a1.z, a1.w};
            float bb[4] = {bv.x, bv.y, bv.z, bv.w};
            #pragma unroll
            for (int i = 0; i < 8; i++)
                #pragma unroll
                for (int j = 0; j < 4; j++)
                    acc[i][j] = fmaf(av[i], bb[j], acc[i][j]);
        }
        __syncthreads();
    }

    const int n = n0 + tx * 4;
    float4 bv = *(const float4*)(bias + n);
    #pragma unroll
    for (int i = 0; i < 8; i++) {
        int b = ty * 8 + i;
        float4 v;
        v.x = acc[i][0] + bv.x; v.y = acc[i][1] + bv.y;
        v.z = acc[i][2] + bv.z; v.w = acc[i][3] + bv.w;
        *(float4*)(out + (size_t)b * TD + (size_t)t * DIM + n) = v;
    }
}

// ---------------------------------------------------------------------------
// rec_kernel: 128 CTAs = 4 groups(16 rows) x 32 d-CTAs(32 dims).
//   256 threads = 32 ks x 8 td; thread: 4 dims over k in [32ks,32ks+32)
//   for all 16 rows (R11 layout). W: 64 ull regs.
//   NO GLOBAL BARRIER: producer (grp,lcta) publishes seq=t+1 (st.release)
//   after step t; consumer lane polls only the producer owning its staged
//   quad (p = tid>>3), then cp.asyncs. Warp-scope chunk waits as before.
// ---------------------------------------------------------------------------
__global__ void __launch_bounds__(256, 1) rec_kernel(const float* __restrict__ lw,
                                                     const float* __restrict__ init,
                                                     float* __restrict__ out) {
    extern __shared__ float sm[];
    float* xs = sm;                 // 16 * 1024 floats (swizzled)
    float* ps = sm + 16 * 1024;     // partials: 512 outputs * PST

    const int cta  = blockIdx.x;
    const int grp  = cta >> 5;
    const int lcta = cta & 31;
    const int b0   = grp * 16;
    const int d0   = lcta * 32;
    const int tid  = threadIdx.x;
    const int ks   = tid >> 3;          // 0..31
    const int td   = tid & 7;           // 0..7
    const int kb   = ks * 32;

    // ---- W tile: 4 dims x 32 k as f32x2 pairs ----
    unsigned long long wp[4][16];
    #pragma unroll
    for (int i = 0; i < 4; i++) {
        const float* r = lw + (size_t)(d0 + td * 4 + i) * DIM + kb;
        #pragma unroll
        for (int q = 0; q < 8; q++) {
            float4 a = *(const float4*)(r + 4 * q);
            F2U t0, t1;
            t0.f = make_float2(a.x, a.y); t1.f = make_float2(a.z, a.w);
            wp[i][2 * q] = t0.u; wp[i][2 * q + 1] = t1.u;
        }
    }

    int off[8];
    #pragma unroll
    for (int q = 0; q < 8; q++) off[q] = (((q + ks) & 7) << 2);

    // staging: this thread's column quad = tid (cols tid*4..+3)
    const int st_slice = tid >> 3;
    const int st_pos   = tid & 7;
    const int st_off   = st_slice * 32 + (((st_pos + st_slice) & 7) << 2);
    const unsigned xs_u32 = (unsigned)__cvta_generic_to_shared(xs) + (unsigned)(st_off * 4);

    // dataflow sync: this lane's staged quad belongs to producer p = tid>>3
    const unsigned* seq_watch = g_seq + (grp * 32 + (tid >> 3)) * 32;
    unsigned* seq_mine = g_seq + (grp * 32 + lcta) * 32;

    // reduced outputs: o = 2*tid, 2*tid+1 -> (row, dim pair)
    const int b_r = tid >> 4;
    const int d_r = (2 * tid) & 31;
    const int len = g_len[b0 + b_r];
    float* orow = out + (size_t)(b0 + b_r) * TD + (d0 + d_r);

    float2 xo = *(const float2*)(init + d0 + d_r);
    float2 uv = __ldcg((const float2*)orow);

    for (int t = 0; t < T_MAX; t++) {
        // ---- wait for this lane's producer, then stage its quad x 16 rows ----
        if (t == 0) {
            float4 v = *(const float4*)(init + tid * 4);
            #pragma unroll 4
            for (int r = 0; r < 16; r++)
                *(float4*)&xs[r * 1024 + st_off] = v;
            __syncwarp();
        } else {
            unsigned v;
            do {
                asm volatile("ld.relaxed.gpu.global.u32 %0, [%1];"
                             : "=r"(v) : "l"(seq_watch) : "memory");
            } while (v < (unsigned)t);
            asm volatile("ld.acquire.gpu.global.u32 %0, [%1];"
                         : "=r"(v) : "l"(seq_watch) : "memory");

            const float* src = out + (size_t)b0 * TD + (size_t)(t - 1) * DIM + tid * 4;
            #pragma unroll
            for (int r = 0; r < 16; r++) {
                asm volatile("cp.async.cg.shared.global [%0], [%1], 16;"
                             :: "r"(xs_u32 + (unsigned)(r * 4096)),
                                "l"(src + (size_t)r * TD) : "memory");
                if ((r & 3) == 3) asm volatile("cp.async.commit_group;" ::: "memory");
            }
        }

        // ---- compute partials: 4 chunks of 4 rows, warp-scope waits ----
        #pragma unroll
        for (int c = 0; c < 4; c++) {
            if (t != 0) {
                if      (c == 0) asm volatile("cp.async.wait_group 3;" ::: "memory");
                else if (c == 1) asm volatile("cp.async.wait_group 2;" ::: "memory");
                else if (c == 2) asm volatile("cp.async.wait_group 1;" ::: "memory");
                else             asm volatile("cp.async.wait_group 0;" ::: "memory");
                __syncwarp();
            }
            #pragma unroll
            for (int rr = 0; rr < 4; rr++) {
                int b = c * 4 + rr;
                const float* xr = xs + b * 1024 + kb;
                unsigned long long a0a = 0ull, a0b = 0ull, a1a = 0ull, a1b = 0ull;
                unsigned long long a2a = 0ull, a2b = 0ull, a3a = 0ull, a3b = 0ull;
                #pragma unroll
                for (int q = 0; q < 8; q++) {
                    ulonglong2 v = *(const ulonglong2*)(xr + off[q]);
                    a0a = fma2(v.x, wp[0][2 * q],     a0a);
                    a0b = fma2(v.y, wp[0][2 * q + 1], a0b);
                    a1a = fma2(v.x, wp[1][2 * q],     a1a);
                    a1b = fma2(v.y, wp[1][2 * q + 1], a1b);
                    a2a = fma2(v.x, wp[2][2 * q],     a2a);
                    a2b = fma2(v.y, wp[2][2 * q + 1], a2b);
                    a3a = fma2(v.x, wp[3][2 * q],     a3a);
                    a3b = fma2(v.y, wp[3][2 * q + 1], a3b);
                }
                F2U s0, s1, s2, s3;
                s0.u = add2(a0a, a0b); s1.u = add2(a1a, a1b);
                s2.u = add2(a2a, a2b); s3.u = add2(a3a, a3b);
                float* pb = ps + (size_t)(b * 32 + td * 4) * PST + ks;
                pb[0 * PST] = s0.f.x + s0.f.y;
                pb[1 * PST] = s1.f.x + s1.f.y;
                pb[2 * PST] = s2.f.x + s2.f.y;
                pb[3 * PST] = s3.f.x + s3.f.y;
            }
        }
        __syncthreads();

        // ---- reduction: outputs 2*tid and 2*tid+1 ----
        float sum0 = 0.f, sum1 = 0.f;
        {
            const float* p0 = ps + (size_t)(2 * tid) * PST;
            const float* p1 = p0 + PST;
            #pragma unroll
            for (int i = 0; i < 32; i++) { sum0 += p0[i]; sum1 += p1[i]; }
        }

        // ---- epilogue: tanh + leak(register) + mask + store ----
        {
            float m = (t < len) ? 1.f : 0.f;
            float2 y;
            y.x = (0.5f * tanhf(uv.x + sum0) + 0.5f * xo.x) * m;
            y.y = (0.5f * tanhf(uv.y + sum1) + 0.5f * xo.y) * m;
            *(float2*)(orow + (size_t)t * DIM) = y;
            xo = y;
        }
        // prefetch next step's u
        {
            int tn = (t + 1 < T_MAX) ? t + 1 : t;
            uv = __ldcg((const float2*)(orow + (size_t)tn * DIM));
        }

        // ---- publish: all CTA stores done -> seq = t+1 (release) ----
        __syncthreads();
        if (tid == 0) {
            asm volatile("st.release.gpu.global.u32 [%0], %1;"
                         :: "l"(seq_mine), "r"((unsigned)(t + 1)) : "memory");
        }
    }
}

// ---------------------------------------------------------------------------
extern "C" void kernel_launch(void* const* d_in, const int* in_sizes, int n_in,
                              void* d_out, int out_size) {
    const float* emb  = (const float*)d_in[0];
    const float* win  = (const float*)d_in[1];
    const float* lw   = (const float*)d_in[2];
    const float* bias = (const float*)d_in[3];
    const float* init = (const float*)d_in[4];
    float* out = (float*)d_out;

    zero_kernel<<<16, 256>>>();
    prep_kernel<<<512, 256>>>(emb);

    dim3 g(T_MAX, DIM / 128);
    ugemm_kernel<<<g, 256>>>(emb, win, bias, out);

    int smem = (16 * 1024 + 512 * PST) * (int)sizeof(float);   // ~130 KB
    cudaFuncSetAttribute(rec_kernel, cudaFuncAttributeMaxDynamicSharedMemorySize, smem);
    rec_kernel<<<NCTA, 256, smem>>>(lw, init, out);

    tail_kernel<<<1, 64>>>(out, out_size);
}

// round 15
// speedup vs baseline: 1.3912x; 1.3912x over previous
#include <cuda_runtime.h>
#include <cstdint>

#define T_MAX 512
#define B_SZ  64
#define IND   300
#define DIM   1024
#define TD    (T_MAX * DIM)
#define NCTA  128
#define GRP_CTAS 32
#define NGRP  4
#define PST   33

__device__ unsigned g_bar[NGRP * T_MAX];
__device__ int      g_len[B_SZ];

union F2U { float2 f; unsigned long long u; };

__device__ __forceinline__ unsigned long long fma2(unsigned long long a,
                                                   unsigned long long b,
                                                   unsigned long long c) {
    unsigned long long d;
    asm("fma.rn.f32x2 %0, %1, %2, %3;" : "=l"(d) : "l"(a), "l"(b), "l"(c));
    return d;
}
__device__ __forceinline__ unsigned long long add2(unsigned long long a,
                                                   unsigned long long b) {
    unsigned long long d;
    asm("add.rn.f32x2 %0, %1, %2;" : "=l"(d) : "l"(a), "l"(b));
    return d;
}

// ---------------------------------------------------------------------------
__global__ void zero_kernel() {
    int i = blockIdx.x * blockDim.x + threadIdx.x;
    if (i < NGRP * T_MAX) g_bar[i] = 0u;
    if (i < B_SZ)         g_len[i] = 0;
}

// ---------------------------------------------------------------------------
__global__ void __launch_bounds__(256) prep_kernel(const float* __restrict__ emb) {
    int b  = blockIdx.x & 63;
    int tq = blockIdx.x >> 6;
    int row = threadIdx.x >> 2;
    int l4  = threadIdx.x & 3;
    int t = tq * 64 + row;
    const float* p = emb + ((size_t)t * B_SZ + b) * IND;
    float s = 0.f;
    for (int i = l4; i < IND; i += 4) s += p[i];
    s += __shfl_xor_sync(~0u, s, 1);
    s += __shfl_xor_sync(~0u, s, 2);
    unsigned ball = __ballot_sync(~0u, (l4 == 0) && (s != 0.f));
    if ((threadIdx.x & 31) == 0) atomicAdd(&g_len[b], __popc(ball));
}

// ---------------------------------------------------------------------------
__global__ void tail_kernel(float* __restrict__ out, int out_size) {
    int b = threadIdx.x;
    long long tail = (long long)T_MAX * B_SZ * DIM;
    if (b < B_SZ && (long long)out_size >= tail + B_SZ)
        out[tail + b] = (float)g_len[b];
}

// ---------------------------------------------------------------------------
// ugemm: u[t,b,:] = input_w @ emb[t,b,:] + bias -> out[b,t,:]
// Tile 64m x 256n, micro 8m x 8n. B split in two 128-col smem arrays so
// both B reads are 16B-stride (conflict-free); A reads warp-uniform.
// 4 LDS.128 per 64 FMA.
// ---------------------------------------------------------------------------
#define KT 32
__global__ void __launch_bounds__(256) ugemm_kernel(const float* __restrict__ emb,
                                                    const float* __restrict__ win,
                                                    const float* __restrict__ bias,
                                                    float* __restrict__ out) {
    __shared__ float As[KT][68];
    __shared__ float Bs0[KT][132];
    __shared__ float Bs1[KT][132];

    const int t  = blockIdx.x;
    const int n0 = blockIdx.y * 256;
    const int tid = threadIdx.x;
    const int tx = tid & 31, ty = tid >> 5;
    const float* arow = emb + (size_t)t * B_SZ * IND;

    float acc[8][8];
    #pragma unroll
    for (int i = 0; i < 8; i++)
        #pragma unroll
        for (int j = 0; j < 8; j++) acc[i][j] = 0.f;

    for (int kk = 0; kk < IND; kk += KT) {
        // stage A: 64 rows x 8 quads
        #pragma unroll
        for (int s = 0; s < 2; s++) {
            int idx = tid + s * 256;
            int row = idx >> 3;
            int f4  = idx & 7;
            int k   = kk + f4 * 4;
            float4 va = make_float4(0.f, 0.f, 0.f, 0.f);
            if (k < IND) va = *(const float4*)(arow + (size_t)row * IND + k);
            As[f4 * 4 + 0][row] = va.x; As[f4 * 4 + 1][row] = va.y;
            As[f4 * 4 + 2][row] = va.z; As[f4 * 4 + 3][row] = va.w;
        }
        // stage B: 256 rows x 8 quads into two 128-row halves
        #pragma unroll
        for (int s = 0; s < 8; s++) {
            int idx = tid + s * 256;
            int row = idx >> 3;
            int f4  = idx & 7;
            int k   = kk + f4 * 4;
            float4 vb = make_float4(0.f, 0.f, 0.f, 0.f);
            if (k < IND) vb = *(const float4*)(win + (size_t)(n0 + row) * IND + k);
            if (row < 128) {
                Bs0[f4 * 4 + 0][row] = vb.x; Bs0[f4 * 4 + 1][row] = vb.y;
                Bs0[f4 * 4 + 2][row] = vb.z; Bs0[f4 * 4 + 3][row] = vb.w;
            } else {
                int r2 = row - 128;
                Bs1[f4 * 4 + 0][r2] = vb.x; Bs1[f4 * 4 + 1][r2] = vb.y;
                Bs1[f4 * 4 + 2][r2] = vb.z; Bs1[f4 * 4 + 3][r2] = vb.w;
            }
        }
        __syncthreads();

        #pragma unroll
        for (int k = 0; k < KT; k++) {
            float4 a0 = *(const float4*)&As[k][ty * 8];
            float4 a1 = *(const float4*)&As[k][ty * 8 + 4];
            float4 b0 = *(const float4*)&Bs0[k][tx * 4];
            float4 b1 = *(const float4*)&Bs1[k][tx * 4];
            float av[8] = {a0.x, a0.y, a0.z, a0.w, a1.x, a1.y, a1.z, a1.w};
            float bv[8] = {b0.x, b0.y, b0.z, b0.w, b1.x, b1.y, b1.z, b1.w};
            #pragma unroll
            for (int i = 0; i < 8; i++)
                #pragma unroll
                for (int j = 0; j < 8; j++)
                    acc[i][j] = fmaf(av[i], bv[j], acc[i][j]);
        }
        __syncthreads();
    }

    const int n  = n0 + tx * 4;
    const int n2 = n + 128;
    float4 bva = *(const float4*)(bias + n);
    float4 bvb = *(const float4*)(bias + n2);
    #pragma unroll
    for (int i = 0; i < 8; i++) {
        int b = ty * 8 + i;
        float4 v0, v1;
        v0.x = acc[i][0] + bva.x; v0.y = acc[i][1] + bva.y;
        v0.z = acc[i][2] + bva.z; v0.w = acc[i][3] + bva.w;
        v1.x = acc[i][4] + bvb.x; v1.y = acc[i][5] + bvb.y;
        v1.z = acc[i][6] + bvb.z; v1.w = acc[i][7] + bvb.w;
        *(float4*)(out + (size_t)b * TD + (size_t)t * DIM + n)  = v0;
        *(float4*)(out + (size_t)b * TD + (size_t)t * DIM + n2) = v1;
    }
}

// ---------------------------------------------------------------------------
// rec_kernel: R11 champion config, verbatim structure.
//   128 CTAs = 4 groups(16 rows) x 32 d-CTAs(32 dims).
//   256 threads = 32 ks x 8 td; thread: 4 dims (d0+4td..+3) over
//   k in [32ks,32ks+32) for all 16 rows. W: 64 ull regs.
//   Warp-local staging via cp.async (4 commit groups), warp-scope waits.
//   Reduction: 2 outputs/thread, 4-way accumulator split.
//   Barrier: per-group single counter (red.release + relaxed poll + acquire).
// ---------------------------------------------------------------------------
__global__ void __launch_bounds__(256, 1) rec_kernel(const float* __restrict__ lw,
                                                     const float* __restrict__ init,
                                                     float* __restrict__ out) {
    extern __shared__ float sm[];
    float* xs = sm;                 // 16 * 1024 floats (swizzled)
    float* ps = sm + 16 * 1024;     // partials: 512 outputs * PST

    const int cta  = blockIdx.x;
    const int grp  = cta >> 5;
    const int lcta = cta & 31;
    const int b0   = grp * 16;
    const int d0   = lcta * 32;
    const int tid  = threadIdx.x;
    const int ks   = tid >> 3;          // 0..31
    const int td   = tid & 7;           // 0..7
    const int kb   = ks * 32;

    // ---- W tile into registers: 4 dims x 32 k as f32x2 pairs ----
    unsigned long long wp[4][16];
    #pragma unroll
    for (int i = 0; i < 4; i++) {
        const float* r = lw + (size_t)(d0 + td * 4 + i) * DIM + kb;
        #pragma unroll
        for (int q = 0; q < 8; q++) {
            float4 a = *(const float4*)(r + 4 * q);
            F2U t0, t1;
            t0.f = make_float2(a.x, a.y); t1.f = make_float2(a.z, a.w);
            wp[i][2 * q] = t0.u; wp[i][2 * q + 1] = t1.u;
        }
    }

    int off[8];
    #pragma unroll
    for (int q = 0; q < 8; q++) off[q] = (((q + ks) & 7) << 2);

    // staging swizzle: this thread's column quad = tid (col tid*4)
    const int st_slice = tid >> 3;
    const int st_pos   = tid & 7;
    const int st_off   = st_slice * 32 + (((st_pos + st_slice) & 7) << 2);
    const unsigned xs_u32 = (unsigned)__cvta_generic_to_shared(xs) + (unsigned)(st_off * 4);

    // this thread's two reduced outputs: o = 2*tid, 2*tid+1 -> (b_r, d_r..d_r+1)
    const int b_r = tid >> 4;
    const int d_r = (2 * tid) & 31;
    const int len = g_len[b0 + b_r];
    float* orow = out + (size_t)(b0 + b_r) * TD + (d0 + d_r);
    unsigned* ctr_base = &g_bar[grp * T_MAX];

    float2 xo = *(const float2*)(init + d0 + d_r);
    float2 uv = __ldcg((const float2*)orow);

    for (int t = 0; t < T_MAX; t++) {
        // ---- stage x_{t-1}: this thread's column (tid*4) for 16 rows ----
        if (t == 0) {
            float4 v = *(const float4*)(init + tid * 4);
            #pragma unroll 4
            for (int r = 0; r < 16; r++)
                *(float4*)&xs[r * 1024 + st_off] = v;
            __syncwarp();
        } else {
            const float* src = out + (size_t)b0 * TD + (size_t)(t - 1) * DIM + tid * 4;
            #pragma unroll
            for (int r = 0; r < 16; r++) {
                asm volatile("cp.async.cg.shared.global [%0], [%1], 16;"
                             :: "r"(xs_u32 + (unsigned)(r * 4096)),
                                "l"(src + (size_t)r * TD) : "memory");
                if ((r & 3) == 3) asm volatile("cp.async.commit_group;" ::: "memory");
            }
        }

        // ---- compute partials: chunks of 4 rows, warp-scope waits ----
        #pragma unroll
        for (int c = 0; c < 4; c++) {
            if (t != 0) {
                if      (c == 0) asm volatile("cp.async.wait_group 3;" ::: "memory");
                else if (c == 1) asm volatile("cp.async.wait_group 2;" ::: "memory");
                else if (c == 2) asm volatile("cp.async.wait_group 1;" ::: "memory");
                else             asm volatile("cp.async.wait_group 0;" ::: "memory");
                __syncwarp();
            }
            #pragma unroll
            for (int rr = 0; rr < 4; rr++) {
                int b = c * 4 + rr;
                const float* xr = xs + b * 1024 + kb;
                unsigned long long a0a = 0ull, a0b = 0ull, a1a = 0ull, a1b = 0ull;
                unsigned long long a2a = 0ull, a2b = 0ull, a3a = 0ull, a3b = 0ull;
                #pragma unroll
                for (int q = 0; q < 8; q++) {
                    ulonglong2 v = *(const ulonglong2*)(xr + off[q]);
                    a0a = fma2(v.x, wp[0][2 * q],     a0a);
                    a0b = fma2(v.y, wp[0][2 * q + 1], a0b);
                    a1a = fma2(v.x, wp[1][2 * q],     a1a);
                    a1b = fma2(v.y, wp[1][2 * q + 1], a1b);
                    a2a = fma2(v.x, wp[2][2 * q],     a2a);
                    a2b = fma2(v.y, wp[2][2 * q + 1], a2b);
                    a3a = fma2(v.x, wp[3][2 * q],     a3a);
                    a3b = fma2(v.y, wp[3][2 * q + 1], a3b);
                }
                F2U s0, s1, s2, s3;
                s0.u = add2(a0a, a0b); s1.u = add2(a1a, a1b);
                s2.u = add2(a2a, a2b); s3.u = add2(a3a, a3b);
                float* pb = ps + (size_t)(b * 32 + td * 4) * PST + ks;
                pb[0 * PST] = s0.f.x + s0.f.y;
                pb[1 * PST] = s1.f.x + s1.f.y;
                pb[2 * PST] = s2.f.x + s2.f.y;
                pb[3 * PST] = s3.f.x + s3.f.y;
            }
        }
        __syncthreads();

        // ---- reduction: outputs 2*tid, 2*tid+1; 4-way accumulator split ----
        float sum0, sum1;
        {
            const float* p0 = ps + (size_t)(2 * tid) * PST;
            const float* p1 = p0 + PST;
            float x0 = 0.f, x1 = 0.f, x2 = 0.f, x3 = 0.f;
            float y0 = 0.f, y1 = 0.f, y2 = 0.f, y3 = 0.f;
            #pragma unroll
            for (int i = 0; i < 32; i += 4) {
                x0 += p0[i];     x1 += p0[i + 1];
                x2 += p0[i + 2]; x3 += p0[i + 3];
                y0 += p1[i];     y1 += p1[i + 1];
                y2 += p1[i + 2]; y3 += p1[i + 3];
            }
            sum0 = (x0 + x1) + (x2 + x3);
            sum1 = (y0 + y1) + (y2 + y3);
        }

        // ---- epilogue: tanh + leak(register) + mask + store ----
        {
            float m = (t < len) ? 1.f : 0.f;
            float2 y;
            y.x = (0.5f * tanhf(uv.x + sum0) + 0.5f * xo.x) * m;
            y.y = (0.5f * tanhf(uv.y + sum1) + 0.5f * xo.y) * m;
            *(float2*)(orow + (size_t)t * DIM) = y;
            xo = y;
        }
        // prefetch next step's u
        {
            int tn = (t + 1 < T_MAX) ? t + 1 : t;
            uv = __ldcg((const float2*)(orow + (size_t)tn * DIM));
        }

        // ---- per-group grid barrier (32 CTAs, single counter) ----
        __syncthreads();
        if (tid == 0) {
            unsigned* ctr = ctr_base + t;
            asm volatile("red.release.gpu.global.add.u32 [%0], 1;" :: "l"(ctr) : "memory");
            unsigned v;
            do {
                asm volatile("ld.relaxed.gpu.global.u32 %0, [%1];" : "=r"(v) : "l"(ctr) : "memory");
            } while (v < GRP_CTAS);
            asm volatile("ld.acquire.gpu.global.u32 %0, [%1];" : "=r"(v) : "l"(ctr) : "memory");
        }
        __syncthreads();
    }
}

// ---------------------------------------------------------------------------
extern "C" void kernel_launch(void* const* d_in, const int* in_sizes, int n_in,
                              void* d_out, int out_size) {
    const float* emb  = (const float*)d_in[0];
    const float* win  = (const float*)d_in[1];
    const float* lw   = (const float*)d_in[2];
    const float* bias = (const float*)d_in[3];
    const float* init = (const float*)d_in[4];
    float* out = (float*)d_out;

    zero_kernel<<<8, 256>>>();
    prep_kernel<<<512, 256>>>(emb);

    dim3 g(T_MAX, DIM / 256);
    ugemm_kernel<<<g, 256>>>(emb, win, bias, out);

    int smem = (16 * 1024 + 512 * PST) * (int)sizeof(float);   // ~130 KB
    cudaFuncSetAttribute(rec_kernel, cudaFuncAttributeMaxDynamicSharedMemorySize, smem);
    rec_kernel<<<NCTA, 256, smem>>>(lw, init, out);

    tail_kernel<<<1, 64>>>(out, out_size);
}

// round 16
// speedup vs baseline: 1.4547x; 1.0456x over previous
#include <cuda_runtime.h>
#include <cuda_bf16.h>
#include <cstdint>

#define T_MAX 512
#define B_SZ  64
#define IND   300
#define DIM   1024
#define TD    (T_MAX * DIM)
#define NCTA  128
#define GRP_CTAS 32
#define NGRP  4

// bf16 hi/lo planes of the state, double-buffered by parity.
// word (b*512 + k/2) holds bf16 pair (k low, k+1 high).
__device__ unsigned g_xhi[2][B_SZ * DIM / 2];
__device__ unsigned g_xlo[2][B_SZ * DIM / 2];
__device__ unsigned g_bar[NGRP * T_MAX];
__device__ int      g_len[B_SZ];

// ---------------------------------------------------------------------------
__device__ __forceinline__ unsigned pack_bf16(float lo_elem, float hi_elem) {
    // low half = lo_elem (lower k), high half = hi_elem
    unsigned short a = __bfloat16_as_ushort(__float2bfloat16_rn(lo_elem));
    unsigned short b = __bfloat16_as_ushort(__float2bfloat16_rn(hi_elem));
    return (unsigned)a | ((unsigned)b << 16);
}
__device__ __forceinline__ float bf16_hi_f(float x) {
    return __bfloat162float(__float2bfloat16_rn(x));
}
__device__ __forceinline__ void mma_bf16(float& d0, float& d1, float& d2, float& d3,
                                         unsigned a0, unsigned a1, unsigned a2, unsigned a3,
                                         unsigned b0, unsigned b1) {
    asm("mma.sync.aligned.m16n8k16.row.col.f32.bf16.bf16.f32 "
        "{%0,%1,%2,%3},{%4,%5,%6,%7},{%8,%9},{%0,%1,%2,%3};"
        : "+f"(d0), "+f"(d1), "+f"(d2), "+f"(d3)
        : "r"(a0), "r"(a1), "r"(a2), "r"(a3), "r"(b0), "r"(b1));
}

// ---------------------------------------------------------------------------
__global__ void zero_kernel() {
    int i = blockIdx.x * blockDim.x + threadIdx.x;
    if (i < NGRP * T_MAX) g_bar[i] = 0u;
    if (i < B_SZ)         g_len[i] = 0;
}

// prefill parity-1 planes with the initial state (x_{-1}) for every batch row
__global__ void __launch_bounds__(256) initplane_kernel(const float* __restrict__ init) {
    int b = blockIdx.x;
    for (int kq = threadIdx.x; kq < 512; kq += 256) {
        float x0 = init[2 * kq], x1 = init[2 * kq + 1];
        float h0 = bf16_hi_f(x0), h1 = bf16_hi_f(x1);
        g_xhi[1][b * 512 + kq] = pack_bf16(x0, x1);
        g_xlo[1][b * 512 + kq] = pack_bf16(x0 - h0, x1 - h1);
    }
}

// ---------------------------------------------------------------------------
__global__ void __launch_bounds__(256) prep_kernel(const float* __restrict__ emb) {
    int b  = blockIdx.x & 63;
    int tq = blockIdx.x >> 6;
    int row = threadIdx.x >> 2;
    int l4  = threadIdx.x & 3;
    int t = tq * 64 + row;
    const float* p = emb + ((size_t)t * B_SZ + b) * IND;
    float s = 0.f;
    for (int i = l4; i < IND; i += 4) s += p[i];
    s += __shfl_xor_sync(~0u, s, 1);
    s += __shfl_xor_sync(~0u, s, 2);
    unsigned ball = __ballot_sync(~0u, (l4 == 0) && (s != 0.f));
    if ((threadIdx.x & 31) == 0) atomicAdd(&g_len[b], __popc(ball));
}

// ---------------------------------------------------------------------------
__global__ void tail_kernel(float* __restrict__ out, int out_size) {
    int b = threadIdx.x;
    long long tail = (long long)T_MAX * B_SZ * DIM;
    if (b < B_SZ && (long long)out_size >= tail + B_SZ)
        out[tail + b] = (float)g_len[b];
}

// ---------------------------------------------------------------------------
// ugemm: R15 winner (64m x 256n, micro 8m x 8n, split-B smem).
// ---------------------------------------------------------------------------
#define KT 32
__global__ void __launch_bounds__(256) ugemm_kernel(const float* __restrict__ emb,
                                                    const float* __restrict__ win,
                                                    const float* __restrict__ bias,
                                                    float* __restrict__ out) {
    __shared__ float As[KT][68];
    __shared__ float Bs0[KT][132];
    __shared__ float Bs1[KT][132];

    const int t  = blockIdx.x;
    const int n0 = blockIdx.y * 256;
    const int tid = threadIdx.x;
    const int tx = tid & 31, ty = tid >> 5;
    const float* arow = emb + (size_t)t * B_SZ * IND;

    float acc[8][8];
    #pragma unroll
    for (int i = 0; i < 8; i++)
        #pragma unroll
        for (int j = 0; j < 8; j++) acc[i][j] = 0.f;

    for (int kk = 0; kk < IND; kk += KT) {
        #pragma unroll
        for (int s = 0; s < 2; s++) {
            int idx = tid + s * 256;
            int row = idx >> 3;
            int f4  = idx & 7;
            int k   = kk + f4 * 4;
            float4 va = make_float4(0.f, 0.f, 0.f, 0.f);
            if (k < IND) va = *(const float4*)(arow + (size_t)row * IND + k);
            As[f4 * 4 + 0][row] = va.x; As[f4 * 4 + 1][row] = va.y;
            As[f4 * 4 + 2][row] = va.z; As[f4 * 4 + 3][row] = va.w;
        }
        #pragma unroll
        for (int s = 0; s < 8; s++) {
            int idx = tid + s * 256;
            int row = idx >> 3;
            int f4  = idx & 7;
            int k   = kk + f4 * 4;
            float4 vb = make_float4(0.f, 0.f, 0.f, 0.f);
            if (k < IND) vb = *(const float4*)(win + (size_t)(n0 + row) * IND + k);
            if (row < 128) {
                Bs0[f4 * 4 + 0][row] = vb.x; Bs0[f4 * 4 + 1][row] = vb.y;
                Bs0[f4 * 4 + 2][row] = vb.z; Bs0[f4 * 4 + 3][row] = vb.w;
            } else {
                int r2 = row - 128;
                Bs1[f4 * 4 + 0][r2] = vb.x; Bs1[f4 * 4 + 1][r2] = vb.y;
                Bs1[f4 * 4 + 2][r2] = vb.z; Bs1[f4 * 4 + 3][r2] = vb.w;
            }
        }
        __syncthreads();

        #pragma unroll
        for (int k = 0; k < KT; k++) {
            float4 a0 = *(const float4*)&As[k][ty * 8];
            float4 a1 = *(const float4*)&As[k][ty * 8 + 4];
            float4 b0 = *(const float4*)&Bs0[k][tx * 4];
            float4 b1 = *(const float4*)&Bs1[k][tx * 4];
            float av[8] = {a0.x, a0.y, a0.z, a0.w, a1.x, a1.y, a1.z, a1.w};
            float bv[8] = {b0.x, b0.y, b0.z, b0.w, b1.x, b1.y, b1.z, b1.w};
            #pragma unroll
            for (int i = 0; i < 8; i++)
                #pragma unroll
                for (int j = 0; j < 8; j++)
                    acc[i][j] = fmaf(av[i], bv[j], acc[i][j]);
        }
        __syncthreads();
    }

    const int n  = n0 + tx * 4;
    const int n2 = n + 128;
    float4 bva = *(const float4*)(bias + n);
    float4 bvb = *(const float4*)(bias + n2);
    #pragma unroll
    for (int i = 0; i < 8; i++) {
        int b = ty * 8 + i;
        float4 v0, v1;
        v0.x = acc[i][0] + bva.x; v0.y = acc[i][1] + bva.y;
        v0.z = acc[i][2] + bva.z; v0.w = acc[i][3] + bva.w;
        v1.x = acc[i][4] + bvb.x; v1.y = acc[i][5] + bvb.y;
        v1.z = acc[i][6] + bvb.z; v1.w = acc[i][7] + bvb.w;
        *(float4*)(out + (size_t)b * TD + (size_t)t * DIM + n)  = v0;
        *(float4*)(out + (size_t)b * TD + (size_t)t * DIM + n2) = v1;
    }
}

// ---------------------------------------------------------------------------
// rec_kernel: tensor-core bf16 3-pass recurrence.
//   128 CTAs = 4 groups(16 rows) x 32 d-CTAs(32 dims). 256 threads = 8 warps.
//   Warp w: n-tile nt = w&3 (8 dims), K-half kh = w>>2 (512 k).
//   Per k16-step: A frags (hi+lo) from bf16 planes in smem, B frags from
//   pre-packed smem W (hi+lo), 3 mma accumulating into fp32 D.
//   2-way split-K reduce via smem; epilogue (warps 0-3) writes fp32 out +
//   bf16 hi/lo planes (parity t&1). Group barrier as in R11.
// SMEM (bytes):
//   xhi 0..33536 (16 rows x 2096B stride), xlo 33536..67072,
//   bh 67072..132608, bl 132608..198144, red 198144..200192
// ---------------------------------------------------------------------------
#define XROW 2096              // bytes per staged plane row (1024*2 + 48 pad)
#define SM_XHI 0
#define SM_XLO 33536
#define SM_BH  67072
#define SM_BL  132608
#define SM_RED 198144
#define SM_TOT 200192

__global__ void __launch_bounds__(256, 1) rec_kernel(const float* __restrict__ lw,
                                                     const float* __restrict__ init,
                                                     float* __restrict__ out) {
    extern __shared__ char sm[];
    char* xhi = sm + SM_XHI;
    char* xlo = sm + SM_XLO;
    unsigned* bh = (unsigned*)(sm + SM_BH);
    unsigned* bl = (unsigned*)(sm + SM_BL);
    float* red = (float*)(sm + SM_RED);

    const int cta  = blockIdx.x;
    const int grp  = cta >> 5;
    const int lcta = cta & 31;
    const int b0   = grp * 16;
    const int d0   = lcta * 32;
    const int tid  = threadIdx.x;
    const int w    = tid >> 5;
    const int lane = tid & 31;
    const int g    = lane >> 2;         // fragment group row
    const int q    = lane & 3;
    const int nt   = w & 3;             // n-tile
    const int kh   = w >> 2;            // K-half

    // ---- build packed W fragments (hi & lo), one time ----
    for (int p = tid; p < 8192; p += 256) {
        int sg  = p >> 7;               // k-step 0..63
        int rst = p & 127;
        int ntb = rst >> 5;
        int l   = rst & 31;
        int d   = d0 + ntb * 8 + (l >> 2);
        int k0  = sg * 16 + 2 * (l & 3);
        const float* wr = lw + (size_t)d * DIM;
        float w00 = wr[k0],     w01 = wr[k0 + 1];
        float w10 = wr[k0 + 8], w11 = wr[k0 + 9];
        float h00 = bf16_hi_f(w00), h01 = bf16_hi_f(w01);
        float h10 = bf16_hi_f(w10), h11 = bf16_hi_f(w11);
        bh[p * 2]     = pack_bf16(w00, w01);
        bh[p * 2 + 1] = pack_bf16(w10, w11);
        bl[p * 2]     = pack_bf16(w00 - h00, w01 - h01);
        bl[p * 2 + 1] = pack_bf16(w10 - h10, w11 - h11);
    }
    __syncthreads();

    // staging source/dest geometry (8 granules per plane per thread)
    const unsigned xhi_u32 = (unsigned)__cvta_generic_to_shared(xhi);
    const unsigned xlo_u32 = (unsigned)__cvta_generic_to_shared(xlo);

    // compute-side A addressing
    const int abase = g * XROW + 4 * q + 1024 * kh;   // byte offset of a0 at s=0
    // B addressing: bytes, step s adds 1024
    const int bbase = (kh * 32 * 4 + nt) * 32 * 8 + lane * 8;

    // epilogue ownership (warps 0-3 only): rows g, g+8; dims d, d+1
    const int d_loc = nt * 8 + 2 * q;
    const int bA = b0 + g, bB = b0 + g + 8;
    const int lenA = g_len[bA], lenB = g_len[bB];
    float* oA = out + (size_t)bA * TD + (d0 + d_loc);
    float* oB = out + (size_t)bB * TD + (d0 + d_loc);
    unsigned* ctr_base = &g_bar[grp * T_MAX];

    float2 xoA = *(const float2*)(init + d0 + d_loc);
    float2 xoB = xoA;
    float2 uvA = __ldcg((const float2*)oA);
    float2 uvB = __ldcg((const float2*)oB);

    for (int t = 0; t < T_MAX; t++) {
        // ---- stage x_{t-1} planes (parity (t+1)&1) ----
        {
            int par = (t + 1) & 1;
            const char* srcH = (const char*)g_xhi[par];
            const char* srcL = (const char*)g_xlo[par];
            #pragma unroll
            for (int i = 0; i < 8; i++) {
                int gr  = tid + 256 * i;        // granule 0..2047
                int row = gr >> 7;
                int c16 = gr & 127;
                unsigned dstH = xhi_u32 + (unsigned)(row * XROW + c16 * 16);
                unsigned dstL = xlo_u32 + (unsigned)(row * XROW + c16 * 16);
                const char* sH = srcH + ((size_t)(b0 + row) * 512 + c16 * 4) * 4;
                const char* sL = srcL + ((size_t)(b0 + row) * 512 + c16 * 4) * 4;
                asm volatile("cp.async.cg.shared.global [%0], [%1], 16;"
                             :: "r"(dstH), "l"(sH) : "memory");
                asm volatile("cp.async.cg.shared.global [%0], [%1], 16;"
                             :: "r"(dstL), "l"(sL) : "memory");
            }
            asm volatile("cp.async.commit_group;" ::: "memory");
            asm volatile("cp.async.wait_group 0;" ::: "memory");
        }
        __syncthreads();

        // ---- tensor-core 3-pass GEMM over this warp's K-half ----
        float c0 = 0.f, c1 = 0.f, c2 = 0.f, c3 = 0.f;
        #pragma unroll 8
        for (int s = 0; s < 32; s++) {
            int aoff = abase + 32 * s;
            unsigned ah0 = *(const unsigned*)(xhi + aoff);
            unsigned ah1 = *(const unsigned*)(xhi + aoff + 8 * XROW);
            unsigned ah2 = *(const unsigned*)(xhi + aoff + 16);
            unsigned ah3 = *(const unsigned*)(xhi + aoff + 8 * XROW + 16);
            unsigned al0 = *(const unsigned*)(xlo + aoff);
            unsigned al1 = *(const unsigned*)(xlo + aoff + 8 * XROW);
            unsigned al2 = *(const unsigned*)(xlo + aoff + 16);
            unsigned al3 = *(const unsigned*)(xlo + aoff + 8 * XROW + 16);
            uint2 bhp = *(const uint2*)((const char*)bh + bbase + 1024 * s);
            uint2 blp = *(const uint2*)((const char*)bl + bbase + 1024 * s);
            mma_bf16(c0, c1, c2, c3, ah0, ah1, ah2, ah3, bhp.x, bhp.y);
            mma_bf16(c0, c1, c2, c3, ah0, ah1, ah2, ah3, blp.x, blp.y);
            mma_bf16(c0, c1, c2, c3, al0, al1, al2, al3, bhp.x, bhp.y);
        }

        // ---- split-K reduce (kh=1 stores, kh=0 adds) ----
        if (kh == 1) {
            float* r = red + nt * 128 + lane * 4;
            r[0] = c0; r[1] = c1; r[2] = c2; r[3] = c3;
        }
        __syncthreads();

        if (kh == 0) {
            const float* r = red + nt * 128 + lane * 4;
            float s0 = c0 + r[0];
            float s1 = c1 + r[1];
            float s2 = c2 + r[2];
            float s3 = c3 + r[3];

            float mA = (t < lenA) ? 1.f : 0.f;
            float mB = (t < lenB) ? 1.f : 0.f;
            float2 yA, yB;
            yA.x = (0.5f * tanhf(uvA.x + s0) + 0.5f * xoA.x) * mA;
            yA.y = (0.5f * tanhf(uvA.y + s1) + 0.5f * xoA.y) * mA;
            yB.x = (0.5f * tanhf(uvB.x + s2) + 0.5f * xoB.x) * mB;
            yB.y = (0.5f * tanhf(uvB.y + s3) + 0.5f * xoB.y) * mB;
            *(float2*)(oA + (size_t)t * DIM) = yA;
            *(float2*)(oB + (size_t)t * DIM) = yB;
            xoA = yA; xoB = yB;

            // bf16 hi/lo planes, parity t&1
            int pw = t & 1;
            int wA = bA * 512 + ((d0 + d_loc) >> 1);
            int wB = bB * 512 + ((d0 + d_loc) >> 1);
            float hAx = bf16_hi_f(yA.x), hAy = bf16_hi_f(yA.y);
            float hBx = bf16_hi_f(yB.x), hBy = bf16_hi_f(yB.y);
            g_xhi[pw][wA] = pack_bf16(yA.x, yA.y);
            g_xlo[pw][wA] = pack_bf16(yA.x - hAx, yA.y - hAy);
            g_xhi[pw][wB] = pack_bf16(yB.x, yB.y);
            g_xlo[pw][wB] = pack_bf16(yB.x - hBx, yB.y - hBy);

            // prefetch next step's u
            int tn = (t + 1 < T_MAX) ? t + 1 : t;
            uvA = __ldcg((const float2*)(oA + (size_t)tn * DIM));
            uvB = __ldcg((const float2*)(oB + (size_t)tn * DIM));
        }

        // ---- per-group grid barrier ----
        __syncthreads();
        if (tid == 0) {
            unsigned* ctr = ctr_base + t;
            asm volatile("red.release.gpu.global.add.u32 [%0], 1;" :: "l"(ctr) : "memory");
            unsigned v;
            do {
                asm volatile("ld.relaxed.gpu.global.u32 %0, [%1];" : "=r"(v) : "l"(ctr) : "memory");
            } while (v < GRP_CTAS);
            asm volatile("ld.acquire.gpu.global.u32 %0, [%1];" : "=r"(v) : "l"(ctr) : "memory");
        }
        __syncthreads();
    }
}

// ---------------------------------------------------------------------------
extern "C" void kernel_launch(void* const* d_in, const int* in_sizes, int n_in,
                              void* d_out, int out_size) {
    const float* emb  = (const float*)d_in[0];
    const float* win  = (const float*)d_in[1];
    const float* lw   = (const float*)d_in[2];
    const float* bias = (const float*)d_in[3];
    const float* init = (const float*)d_in[4];
    float* out = (float*)d_out;

    zero_kernel<<<8, 256>>>();
    prep_kernel<<<512, 256>>>(emb);
    initplane_kernel<<<B_SZ, 256>>>(init);

    dim3 g(T_MAX, DIM / 256);
    ugemm_kernel<<<g, 256>>>(emb, win, bias, out);

    cudaFuncSetAttribute(rec_kernel, cudaFuncAttributeMaxDynamicSharedMemorySize, SM_TOT);
    rec_kernel<<<NCTA, 256, SM_TOT>>>(lw, init, out);

    tail_kernel<<<1, 64>>>(out, out_size);
}

// round 17
// speedup vs baseline: 1.4730x; 1.0126x over previous
#include <cuda_runtime.h>
#include <cuda_bf16.h>
#include <cstdint>

#define T_MAX 512
#define B_SZ  64
#define IND   300
#define DIM   1024
#define TD    (T_MAX * DIM)
#define NCTA  128
#define GRP_CTAS 32
#define NGRP  4

// bf16 hi/lo planes of the state, double-buffered by parity.
__device__ unsigned g_xhi[2][B_SZ * DIM / 2];
__device__ unsigned g_xlo[2][B_SZ * DIM / 2];
__device__ unsigned g_bar[NGRP * T_MAX];
__device__ int      g_len[B_SZ];

// ---------------------------------------------------------------------------
__device__ __forceinline__ unsigned pack_bf16(float lo_elem, float hi_elem) {
    unsigned short a = __bfloat16_as_ushort(__float2bfloat16_rn(lo_elem));
    unsigned short b = __bfloat16_as_ushort(__float2bfloat16_rn(hi_elem));
    return (unsigned)a | ((unsigned)b << 16);
}
__device__ __forceinline__ float bf16_hi_f(float x) {
    return __bfloat162float(__float2bfloat16_rn(x));
}
__device__ __forceinline__ void mma_bf16(float& d0, float& d1, float& d2, float& d3,
                                         unsigned a0, unsigned a1, unsigned a2, unsigned a3,
                                         unsigned b0, unsigned b1) {
    asm("mma.sync.aligned.m16n8k16.row.col.f32.bf16.bf16.f32 "
        "{%0,%1,%2,%3},{%4,%5,%6,%7},{%8,%9},{%0,%1,%2,%3};"
        : "+f"(d0), "+f"(d1), "+f"(d2), "+f"(d3)
        : "r"(a0), "r"(a1), "r"(a2), "r"(a3), "r"(b0), "r"(b1));
}
__device__ __forceinline__ void ldsm_x4(unsigned& r0, unsigned& r1,
                                        unsigned& r2, unsigned& r3, unsigned addr) {
    asm volatile("ldmatrix.sync.aligned.m8n8.x4.shared.b16 {%0,%1,%2,%3}, [%4];"
                 : "=r"(r0), "=r"(r1), "=r"(r2), "=r"(r3) : "r"(addr));
}

// ---------------------------------------------------------------------------
__global__ void zero_kernel() {
    int i = blockIdx.x * blockDim.x + threadIdx.x;
    if (i < NGRP * T_MAX) g_bar[i] = 0u;
    if (i < B_SZ)         g_len[i] = 0;
}

// prefill parity-1 planes with the initial state for every batch row
__global__ void __launch_bounds__(256) initplane_kernel(const float* __restrict__ init) {
    int b = blockIdx.x;
    for (int kq = threadIdx.x; kq < 512; kq += 256) {
        float x0 = init[2 * kq], x1 = init[2 * kq + 1];
        float h0 = bf16_hi_f(x0), h1 = bf16_hi_f(x1);
        g_xhi[1][b * 512 + kq] = pack_bf16(x0, x1);
        g_xlo[1][b * 512 + kq] = pack_bf16(x0 - h0, x1 - h1);
    }
}

// ---------------------------------------------------------------------------
__global__ void __launch_bounds__(256) prep_kernel(const float* __restrict__ emb) {
    int b  = blockIdx.x & 63;
    int tq = blockIdx.x >> 6;
    int row = threadIdx.x >> 2;
    int l4  = threadIdx.x & 3;
    int t = tq * 64 + row;
    const float* p = emb + ((size_t)t * B_SZ + b) * IND;
    float s = 0.f;
    for (int i = l4; i < IND; i += 4) s += p[i];
    s += __shfl_xor_sync(~0u, s, 1);
    s += __shfl_xor_sync(~0u, s, 2);
    unsigned ball = __ballot_sync(~0u, (l4 == 0) && (s != 0.f));
    if ((threadIdx.x & 31) == 0) atomicAdd(&g_len[b], __popc(ball));
}

// ---------------------------------------------------------------------------
__global__ void tail_kernel(float* __restrict__ out, int out_size) {
    int b = threadIdx.x;
    long long tail = (long long)T_MAX * B_SZ * DIM;
    if (b < B_SZ && (long long)out_size >= tail + B_SZ)
        out[tail + b] = (float)g_len[b];
}

// ---------------------------------------------------------------------------
// ugemm: R15 winner (64m x 256n, micro 8m x 8n, split-B smem). At FFMA roofline.
// ---------------------------------------------------------------------------
#define KT 32
__global__ void __launch_bounds__(256) ugemm_kernel(const float* __restrict__ emb,
                                                    const float* __restrict__ win,
                                                    const float* __restrict__ bias,
                                                    float* __restrict__ out) {
    __shared__ float As[KT][68];
    __shared__ float Bs0[KT][132];
    __shared__ float Bs1[KT][132];

    const int t  = blockIdx.x;
    const int n0 = blockIdx.y * 256;
    const int tid = threadIdx.x;
    const int tx = tid & 31, ty = tid >> 5;
    const float* arow = emb + (size_t)t * B_SZ * IND;

    float acc[8][8];
    #pragma unroll
    for (int i = 0; i < 8; i++)
        #pragma unroll
        for (int j = 0; j < 8; j++) acc[i][j] = 0.f;

    for (int kk = 0; kk < IND; kk += KT) {
        #pragma unroll
        for (int s = 0; s < 2; s++) {
            int idx = tid + s * 256;
            int row = idx >> 3;
            int f4  = idx & 7;
            int k   = kk + f4 * 4;
            float4 va = make_float4(0.f, 0.f, 0.f, 0.f);
            if (k < IND) va = *(const float4*)(arow + (size_t)row * IND + k);
            As[f4 * 4 + 0][row] = va.x; As[f4 * 4 + 1][row] = va.y;
            As[f4 * 4 + 2][row] = va.z; As[f4 * 4 + 3][row] = va.w;
        }
        #pragma unroll
        for (int s = 0; s < 8; s++) {
            int idx = tid + s * 256;
            int row = idx >> 3;
            int f4  = idx & 7;
            int k   = kk + f4 * 4;
            float4 vb = make_float4(0.f, 0.f, 0.f, 0.f);
            if (k < IND) vb = *(const float4*)(win + (size_t)(n0 + row) * IND + k);
            if (row < 128) {
                Bs0[f4 * 4 + 0][row] = vb.x; Bs0[f4 * 4 + 1][row] = vb.y;
                Bs0[f4 * 4 + 2][row] = vb.z; Bs0[f4 * 4 + 3][row] = vb.w;
            } else {
                int r2 = row - 128;
                Bs1[f4 * 4 + 0][r2] = vb.x; Bs1[f4 * 4 + 1][r2] = vb.y;
                Bs1[f4 * 4 + 2][r2] = vb.z; Bs1[f4 * 4 + 3][r2] = vb.w;
            }
        }
        __syncthreads();

        #pragma unroll
        for (int k = 0; k < KT; k++) {
            float4 a0 = *(const float4*)&As[k][ty * 8];
            float4 a1 = *(const float4*)&As[k][ty * 8 + 4];
            float4 b0 = *(const float4*)&Bs0[k][tx * 4];
            float4 b1 = *(const float4*)&Bs1[k][tx * 4];
            float av[8] = {a0.x, a0.y, a0.z, a0.w, a1.x, a1.y, a1.z, a1.w};
            float bv[8] = {b0.x, b0.y, b0.z, b0.w, b1.x, b1.y, b1.z, b1.w};
            #pragma unroll
            for (int i = 0; i < 8; i++)
                #pragma unroll
                for (int j = 0; j < 8; j++)
                    acc[i][j] = fmaf(av[i], bv[j], acc[i][j]);
        }
        __syncthreads();
    }

    const int n  = n0 + tx * 4;
    const int n2 = n + 128;
    float4 bva = *(const float4*)(bias + n);
    float4 bvb = *(const float4*)(bias + n2);
    #pragma unroll
    for (int i = 0; i < 8; i++) {
        int b = ty * 8 + i;
        float4 v0, v1;
        v0.x = acc[i][0] + bva.x; v0.y = acc[i][1] + bva.y;
        v0.z = acc[i][2] + bva.z; v0.w = acc[i][3] + bva.w;
        v1.x = acc[i][4] + bvb.x; v1.y = acc[i][5] + bvb.y;
        v1.z = acc[i][6] + bvb.z; v1.w = acc[i][7] + bvb.w;
        *(float4*)(out + (size_t)b * TD + (size_t)t * DIM + n)  = v0;
        *(float4*)(out + (size_t)b * TD + (size_t)t * DIM + n2) = v1;
    }
}

// ---------------------------------------------------------------------------
// rec_kernel: bf16 3-pass tensor-core recurrence (R16) + ldmatrix A frags +
// epilogue split across all 8 warps (kh=0 -> row g, kh=1 -> row g+8).
// ---------------------------------------------------------------------------
#define XROW 2096
#define SM_XHI 0
#define SM_XLO 33536
#define SM_BH  67072
#define SM_BL  132608
#define SM_RED 198144
#define SM_TOT 200192

__global__ void __launch_bounds__(256, 1) rec_kernel(const float* __restrict__ lw,
                                                     const float* __restrict__ init,
                                                     float* __restrict__ out) {
    extern __shared__ char sm[];
    char* xhi = sm + SM_XHI;
    char* xlo = sm + SM_XLO;
    unsigned* bh = (unsigned*)(sm + SM_BH);
    unsigned* bl = (unsigned*)(sm + SM_BL);
    float* red0 = (float*)(sm + SM_RED);          // kh1 -> kh0 (c0,c1)
    float* red1 = (float*)(sm + SM_RED) + 256;    // kh0 -> kh1 (c2,c3)

    const int cta  = blockIdx.x;
    const int grp  = cta >> 5;
    const int lcta = cta & 31;
    const int b0   = grp * 16;
    const int d0   = lcta * 32;
    const int tid  = threadIdx.x;
    const int w    = tid >> 5;
    const int lane = tid & 31;
    const int g    = lane >> 2;
    const int q    = lane & 3;
    const int nt   = w & 3;
    const int kh   = w >> 2;

    // ---- build packed W fragments (hi & lo), one time ----
    for (int p = tid; p < 8192; p += 256) {
        int sg  = p >> 7;
        int rst = p & 127;
        int ntb = rst >> 5;
        int l   = rst & 31;
        int d   = d0 + ntb * 8 + (l >> 2);
        int k0  = sg * 16 + 2 * (l & 3);
        const float* wr = lw + (size_t)d * DIM;
        float w00 = wr[k0],     w01 = wr[k0 + 1];
        float w10 = wr[k0 + 8], w11 = wr[k0 + 9];
        float h00 = bf16_hi_f(w00), h01 = bf16_hi_f(w01);
        float h10 = bf16_hi_f(w10), h11 = bf16_hi_f(w11);
        bh[p * 2]     = pack_bf16(w00, w01);
        bh[p * 2 + 1] = pack_bf16(w10, w11);
        bl[p * 2]     = pack_bf16(w00 - h00, w01 - h01);
        bl[p * 2 + 1] = pack_bf16(w10 - h10, w11 - h11);
    }
    __syncthreads();

    const unsigned xhi_u32 = (unsigned)__cvta_generic_to_shared(xhi);
    const unsigned xlo_u32 = (unsigned)__cvta_generic_to_shared(xlo);

    // ldmatrix per-lane base: lanes 0-15 -> rows 0-15, lanes 16-31 -> +16B col half
    const unsigned lm_off = (unsigned)((lane & 15) * XROW + kh * 1024 + (lane >> 4) * 16);
    // B addressing (bytes), step s adds 1024
    const int bbase = (kh * 32 * 4 + nt) * 32 * 8 + lane * 8;

    // epilogue: warp owns row g (kh=0) or g+8 (kh=1); dims d_loc..+1
    const int d_loc = nt * 8 + 2 * q;
    const int my_b  = b0 + g + kh * 8;
    const int my_len = g_len[my_b];
    float* my_o = out + (size_t)my_b * TD + (d0 + d_loc);
    const int ridx = (nt * 32 + lane) * 2;
    unsigned* ctr_base = &g_bar[grp * T_MAX];

    float2 xo = *(const float2*)(init + d0 + d_loc);
    float2 uv = __ldcg((const float2*)my_o);

    for (int t = 0; t < T_MAX; t++) {
        // ---- stage x_{t-1} planes (parity (t+1)&1) ----
        {
            int par = (t + 1) & 1;
            const char* srcH = (const char*)g_xhi[par];
            const char* srcL = (const char*)g_xlo[par];
            #pragma unroll
            for (int i = 0; i < 8; i++) {
                int gr  = tid + 256 * i;
                int row = gr >> 7;
                int c16 = gr & 127;
                unsigned dstH = xhi_u32 + (unsigned)(row * XROW + c16 * 16);
                unsigned dstL = xlo_u32 + (unsigned)(row * XROW + c16 * 16);
                const char* sH = srcH + ((size_t)(b0 + row) * 512 + c16 * 4) * 4;
                const char* sL = srcL + ((size_t)(b0 + row) * 512 + c16 * 4) * 4;
                asm volatile("cp.async.cg.shared.global [%0], [%1], 16;"
                             :: "r"(dstH), "l"(sH) : "memory");
                asm volatile("cp.async.cg.shared.global [%0], [%1], 16;"
                             :: "r"(dstL), "l"(sL) : "memory");
            }
            asm volatile("cp.async.commit_group;" ::: "memory");
            asm volatile("cp.async.wait_group 0;" ::: "memory");
        }
        __syncthreads();

        // ---- tensor-core 3-pass GEMM over this warp's K-half ----
        float c0 = 0.f, c1 = 0.f, c2 = 0.f, c3 = 0.f;
        #pragma unroll 8
        for (int s = 0; s < 32; s++) {
            unsigned ah0, ah1, ah2, ah3, al0, al1, al2, al3;
            ldsm_x4(ah0, ah1, ah2, ah3, xhi_u32 + lm_off + 32 * s);
            ldsm_x4(al0, al1, al2, al3, xlo_u32 + lm_off + 32 * s);
            uint2 bhp = *(const uint2*)((const char*)bh + bbase + 1024 * s);
            uint2 blp = *(const uint2*)((const char*)bl + bbase + 1024 * s);
            mma_bf16(c0, c1, c2, c3, ah0, ah1, ah2, ah3, bhp.x, bhp.y);
            mma_bf16(c0, c1, c2, c3, ah0, ah1, ah2, ah3, blp.x, blp.y);
            mma_bf16(c0, c1, c2, c3, al0, al1, al2, al3, bhp.x, bhp.y);
        }

        // ---- cross-warp reduce: each warp stores the half it doesn't own ----
        if (kh == 0) {
            red1[ridx] = c2; red1[ridx + 1] = c3;
        } else {
            red0[ridx] = c0; red0[ridx + 1] = c1;
        }
        __syncthreads();

        // ---- epilogue on ALL warps (2 outputs each) ----
        {
            float s0, s1;
            if (kh == 0) { s0 = c0 + red0[ridx]; s1 = c1 + red0[ridx + 1]; }
            else         { s0 = c2 + red1[ridx]; s1 = c3 + red1[ridx + 1]; }

            float m = (t < my_len) ? 1.f : 0.f;
            float2 y;
            y.x = (0.5f * tanhf(uv.x + s0) + 0.5f * xo.x) * m;
            y.y = (0.5f * tanhf(uv.y + s1) + 0.5f * xo.y) * m;
            *(float2*)(my_o + (size_t)t * DIM) = y;
            xo = y;

            int pw = t & 1;
            int wi = my_b * 512 + ((d0 + d_loc) >> 1);
            float hx = bf16_hi_f(y.x), hy = bf16_hi_f(y.y);
            g_xhi[pw][wi] = pack_bf16(y.x, y.y);
            g_xlo[pw][wi] = pack_bf16(y.x - hx, y.y - hy);

            int tn = (t + 1 < T_MAX) ? t + 1 : t;
            uv = __ldcg((const float2*)(my_o + (size_t)tn * DIM));
        }

        // ---- per-group grid barrier ----
        __syncthreads();
        if (tid == 0) {
            unsigned* ctr = ctr_base + t;
            asm volatile("red.release.gpu.global.add.u32 [%0], 1;" :: "l"(ctr) : "memory");
            unsigned v;
            do {
                asm volatile("ld.relaxed.gpu.global.u32 %0, [%1];" : "=r"(v) : "l"(ctr) : "memory");
            } while (v < GRP_CTAS);
            asm volatile("ld.acquire.gpu.global.u32 %0, [%1];" : "=r"(v) : "l"(ctr) : "memory");
        }
        __syncthreads();
    }
}

// ---------------------------------------------------------------------------
extern "C" void kernel_launch(void* const* d_in, const int* in_sizes, int n_in,
                              void* d_out, int out_size) {
    const float* emb  = (const float*)d_in[0];
    const float* win  = (const float*)d_in[1];
    const float* lw   = (const float*)d_in[2];
    const float* bias = (const float*)d_in[3];
    const float* init = (const float*)d_in[4];
    float* out = (float*)d_out;

    zero_kernel<<<8, 256>>>();
    prep_kernel<<<512, 256>>>(emb);
    initplane_kernel<<<B_SZ, 256>>>(init);

    dim3 g(T_MAX, DIM / 256);
    ugemm_kernel<<<g, 256>>>(emb, win, bias, out);

    cudaFuncSetAttribute(rec_kernel, cudaFuncAttributeMaxDynamicSharedMemorySize, SM_TOT);
    rec_kernel<<<NCTA, 256, SM_TOT>>>(lw, init, out);

    tail_kernel<<<1, 64>>>(out, out_size);
}